// round 10
// baseline (speedup 1.0000x reference)
#include <cuda_runtime.h>
#include <cuda_fp16.h>
#include <math.h>

#define NQ 8
#define NF 256
#define NPAIR 28
#define STRIDE 32
#define MAXN 50176
#define MAXE 1600000
#define TILE 4096

// ---------------- static scratch ----------------
__device__ __half g_sfeat[MAXN * STRIDE]; // features fp16 (unscaled, then scaled)
__device__ int    g_cnt [MAXN];
__device__ int    g_off [MAXN];
__device__ int    g_rank[MAXE];           // rank of edge within its dst segment
__device__ int    g_srcidx[MAXE];
__device__ float  g_dinv[MAXN];
__device__ float  g_coefs[NPAIR * 4];     // (B00, -B00, 2ReB01, pad)
__device__ float  g_G[784];
__device__ int    g_tick;

// ---------------- complex 2x2 helpers ----------------
__device__ __forceinline__ float2 cmul(float2 a, float2 b) {
    return make_float2(a.x * b.x - a.y * b.y, a.x * b.y + a.y * b.x);
}
__device__ __forceinline__ float2 cadd(float2 a, float2 b) {
    return make_float2(a.x + b.x, a.y + b.y);
}
__device__ __forceinline__ void mm2(const float2* A, const float2* B, float2* C) {
#pragma unroll
    for (int i = 0; i < 2; i++)
#pragma unroll
        for (int j = 0; j < 2; j++)
            C[i * 2 + j] = cadd(cmul(A[i * 2 + 0], B[0 * 2 + j]),
                                cmul(A[i * 2 + 1], B[1 * 2 + j]));
}

__device__ __forceinline__ float dot4(float4 a, float4 b) {
    return a.x * b.x + a.y * b.y + a.z * b.z + a.w * b.w;
}

__device__ __forceinline__ int pair_a(int f) {
    return (f < 7) ? 0 : (f < 13) ? 1 : (f < 18) ? 2 : (f < 22) ? 3
         : (f < 25) ? 4 : (f < 27) ? 5 : 6;
}

// K1: coefficients + zero cnt/G/tick
__global__ void k_setup(const float* __restrict__ qw, int N) {
    int g = blockIdx.x * blockDim.x + threadIdx.x;
    if (g < N) g_cnt[g] = 0;
    if (g < 784) g_G[g] = 0.f;
    if (g == 800) g_tick = 0;
    if (g >= NPAIR) return;
    const float* p = qw + 6 * g;
    float2 M[4], T[4], R[4];
    float c, s;
    c = cosf(0.5f * p[0]); s = sinf(0.5f * p[0]);
    M[0] = make_float2(c, 0); M[1] = make_float2(0, -s);
    M[2] = make_float2(0, -s); M[3] = make_float2(c, 0);            // Rx(p0)
    c = cosf(0.5f * p[1]); s = sinf(0.5f * p[1]);
    R[0] = make_float2(c, 0); R[1] = make_float2(-s, 0);
    R[2] = make_float2(s, 0); R[3] = make_float2(c, 0);
    mm2(R, M, T);                                                   // Ry(p1)
    c = cosf(0.5f * p[2]); s = sinf(0.5f * p[2]);
    R[0] = make_float2(c, -s); R[1] = make_float2(0, 0);
    R[2] = make_float2(0, 0);  R[3] = make_float2(c, s);
    mm2(R, T, M);                                                   // Rz(p2)
    c = cosf(0.5f * p[3]); s = sinf(0.5f * p[3]);
    R[0] = make_float2(c, 0); R[1] = make_float2(0, -s);
    R[2] = make_float2(0, -s); R[3] = make_float2(c, 0);
    mm2(R, M, T);                                                   // Rx(p3)
    c = cosf(0.5f * p[4]); s = sinf(0.5f * p[4]);
    R[0] = make_float2(c, 0); R[1] = make_float2(-s, 0);
    R[2] = make_float2(s, 0); R[3] = make_float2(c, 0);
    mm2(R, T, M);                                                   // Ry(p4)
    c = cosf(0.5f * p[5]); s = sinf(0.5f * p[5]);
    R[0] = make_float2(c, -s); R[1] = make_float2(0, 0);
    R[2] = make_float2(0, 0);  R[3] = make_float2(c, s);
    mm2(R, M, T);                                                   // T = A
    float b00 = T[0].x * T[0].x + T[0].y * T[0].y
              - (T[2].x * T[2].x + T[2].y * T[2].y);
    float b01x2 = 2.f * (T[0].x * T[1].x + T[0].y * T[1].y
                       - T[2].x * T[3].x - T[2].y * T[3].y);
    g_coefs[g * 4 + 0] = b00;
    g_coefs[g * 4 + 1] = -b00;
    g_coefs[g * 4 + 2] = b01x2;
}

// feat body: 4 nodes/warp, 8 lanes/node, UNSCALED fp16 output.
__device__ __forceinline__ void feat_body(const float* __restrict__ x, int N,
                                          int blk) {
    __shared__ float4 smw[8][256];
    int lane = threadIdx.x & 31;
    int warp = threadIdx.x >> 5;
    int g    = lane & 7;
    int sub  = lane >> 3;
    int node = blk * 32 + warp * 4 + sub;
    int nclamp = node < N ? node : N - 1;

    const float4* xr = (const float4*)(x + (size_t)nclamp * NF);
    float4 v[8];
#pragma unroll
    for (int sg = 0; sg < 8; sg++) v[sg] = xr[sg * 8 + g];

    float4* sw = &smw[warp][sub * 64];
#pragma unroll
    for (int sg = 0; sg < 8; sg++) sw[sg * 8 + g] = v[sg];
    __syncwarp();

    float s2 = 0.f, p0 = 0.f, p1 = 0.f, p2 = 0.f, p6 = 0.f, t6 = 0.f;
#pragma unroll
    for (int sg = 0; sg < 8; sg++) {
        float4 a = v[sg];
        float nn = dot4(a, a);
        s2 += nn;
        p0 += (sg & 4) ? -nn : nn;
        p1 += (sg & 2) ? -nn : nn;
        p2 += (sg & 1) ? -nn : nn;
        p6 += a.x * a.x + a.y * a.y - a.z * a.z - a.w * a.w;
        t6 += a.x * a.z + a.y * a.w;
    }
    float t0 = dot4(v[0], v[4]) + dot4(v[1], v[5])
             + dot4(v[2], v[6]) + dot4(v[3], v[7]);
    float t1 = dot4(v[0], v[2]) + dot4(v[1], v[3])
             + dot4(v[4], v[6]) + dot4(v[5], v[7]);
    float t2 = dot4(v[0], v[1]) + dot4(v[2], v[3])
             + dot4(v[4], v[5]) + dot4(v[6], v[7]);

    float t3 = 0.f, t4 = 0.f, t5 = 0.f;
#pragma unroll
    for (int sg = 0; sg < 8; sg++) t3 += dot4(v[sg], sw[sg * 8 + (g ^ 4)]);
#pragma unroll
    for (int sg = 0; sg < 8; sg++) t4 += dot4(v[sg], sw[sg * 8 + (g ^ 2)]);
#pragma unroll
    for (int sg = 0; sg < 8; sg++) t5 += dot4(v[sg], sw[sg * 8 + (g ^ 1)]);

#define RED8(a) { a += __shfl_xor_sync(~0u, a, 1); \
                  a += __shfl_xor_sync(~0u, a, 2); \
                  a += __shfl_xor_sync(~0u, a, 4); }
    RED8(p0) RED8(p1) RED8(p2) RED8(p6)
    RED8(t0) RED8(t1) RED8(t2) RED8(t6)
    RED8(t3) RED8(t4) RED8(t5)
    t3 *= 0.5f; t4 *= 0.5f; t5 *= 0.5f;

    float r0  = s2 + __shfl_xor_sync(~0u, s2, 1);
    float r1  = s2 + __shfl_xor_sync(~0u, s2, 2);
    float r01 = r0 + __shfl_xor_sync(~0u, r0, 2);
    float r02 = r0 + __shfl_xor_sync(~0u, r0, 4);
    float r12 = r1 + __shfl_xor_sync(~0u, r1, 4);
    float ssr = r01 + __shfl_xor_sync(~0u, r01, 4);
    float u3  = r01 - __shfl_xor_sync(~0u, r01, 4);
    float u4  = r02 - __shfl_xor_sync(~0u, r02, 2);
    float u5  = r12 - __shfl_xor_sync(~0u, r12, 1);
    float q3v = ((g >> 2) & 1) ? -u3 : u3;
    float q4v = ((g >> 1) & 1) ? -u4 : u4;
    float q5v = (g & 1) ? -u5 : u5;

    float smv[7] = {p0, p1, p2, q3v, q4v, q5v, p6};
    float tqv[7] = {t0, t1, t2, t3, t4, t5, t6};

    float inv_ss = 1.f / ssr;
#pragma unroll
    for (int k = 0; k < 4; k++) {
        int f = g + 8 * k;
        float outv = 0.f;
        if (f < NPAIR) {
            int a = pair_a(f);
            float S = 0.f, Tv = 0.f;
#pragma unroll
            for (int q = 0; q < 7; q++)
                if (a == q) { S = smv[q]; Tv = tqv[q]; }
            float S0 = 0.5f * (ssr + S);
            float S1 = ssr - S0;
            float4 co = *(const float4*)&g_coefs[f * 4];
            float e = (co.x * S0 + co.y * S1 + co.z * Tv) * inv_ss;
            outv = 0.5f + 0.5f * e;
        }
        if (node < N) g_sfeat[(size_t)node * STRIDE + f] = __float2half(outv);
    }
#undef RED8
}

// hist body: 8 edges/thread, atomic return value = rank within dst segment
__device__ __forceinline__ void hist_body(const int* __restrict__ dst, int E,
                                          int N, int blk) {
    int t = blk * 256 + threadIdx.x;
    int E8 = E >> 3;
    if (t < E8) {
        int4 d0 = ((const int4*)dst)[2 * t];
        int4 d1 = ((const int4*)dst)[2 * t + 1];
        int4 r0, r1;
        r0.x = ((unsigned)d0.x < (unsigned)N) ? atomicAdd(&g_cnt[d0.x], 1) : 0;
        r0.y = ((unsigned)d0.y < (unsigned)N) ? atomicAdd(&g_cnt[d0.y], 1) : 0;
        r0.z = ((unsigned)d0.z < (unsigned)N) ? atomicAdd(&g_cnt[d0.z], 1) : 0;
        r0.w = ((unsigned)d0.w < (unsigned)N) ? atomicAdd(&g_cnt[d0.w], 1) : 0;
        r1.x = ((unsigned)d1.x < (unsigned)N) ? atomicAdd(&g_cnt[d1.x], 1) : 0;
        r1.y = ((unsigned)d1.y < (unsigned)N) ? atomicAdd(&g_cnt[d1.y], 1) : 0;
        r1.z = ((unsigned)d1.z < (unsigned)N) ? atomicAdd(&g_cnt[d1.z], 1) : 0;
        r1.w = ((unsigned)d1.w < (unsigned)N) ? atomicAdd(&g_cnt[d1.w], 1) : 0;
        ((int4*)g_rank)[2 * t]     = r0;
        ((int4*)g_rank)[2 * t + 1] = r1;
    }
    if (t == 0)
        for (int e = E8 * 8; e < E; e++) {
            int d = dst[e];
            g_rank[e] = ((unsigned)d < (unsigned)N) ? atomicAdd(&g_cnt[d], 1) : 0;
        }
}

// K2: feat || hist (both depend only on setup)
__global__ void k_feathist(const float* __restrict__ x,
                           const int* __restrict__ dst, int E, int N,
                           int nFeatBlk) {
    if ((int)blockIdx.x < nFeatBlk) feat_body(x, N, blockIdx.x);
    else                            hist_body(dst, E, N, blockIdx.x - nFeatBlk);
}

// K3: fused scan -> off, dinv
__global__ void k_scan(int N) {
    __shared__ int sred[32];
    __shared__ int swsum[32];
    __shared__ int swpre[32];
    __shared__ int s_prefix;
    int b = blockIdx.x, t = threadIdx.x;
    int lane = t & 31, warp = t >> 5;
    int ps = 0;
    for (int i = t; i < b * TILE; i += 1024) ps += g_cnt[i];
#pragma unroll
    for (int off = 16; off; off >>= 1) ps += __shfl_xor_sync(~0u, ps, off);
    if (lane == 0) sred[warp] = ps;
    __syncthreads();
    if (warp == 0) {
        int v = sred[lane];
#pragma unroll
        for (int off = 16; off; off >>= 1) v += __shfl_xor_sync(~0u, v, off);
        if (lane == 0) s_prefix = v;
    }
    int base = b * TILE + t * 4;
    int v[4], pre[4];
    int run = 0;
#pragma unroll
    for (int k = 0; k < 4; k++) {
        int i = base + k;
        v[k] = (i < N) ? g_cnt[i] : 0;
        pre[k] = run;
        run += v[k];
    }
    int incl = run;
#pragma unroll
    for (int off = 1; off < 32; off <<= 1) {
        int u = __shfl_up_sync(~0u, incl, off);
        if (lane >= off) incl += u;
    }
    if (lane == 31) swsum[warp] = incl;
    int texcl = incl - run;
    __syncthreads();
    if (warp == 0) {
        int w = swsum[lane];
        int wi = w;
#pragma unroll
        for (int off = 1; off < 32; off <<= 1) {
            int u = __shfl_up_sync(~0u, wi, off);
            if (lane >= off) wi += u;
        }
        swpre[lane] = wi - w;
    }
    __syncthreads();
    int tilebase = s_prefix + swpre[warp] + texcl;
#pragma unroll
    for (int k = 0; k < 4; k++) {
        int i = base + k;
        if (i < N) {
            g_off[i] = tilebase + pre[k];
            g_dinv[i] = rsqrtf((float)(v[k] + 1));
        }
    }
}

// scale body: sfeat *= dinv[node], half2 granularity
__device__ __forceinline__ void scale_body(int N, int blk) {
    int i = blk * 256 + threadIdx.x;       // half2 index
    if (i >= N * (STRIDE / 2)) return;
    int node = i >> 4;
    float d = g_dinv[node];
    __half2 hv = ((__half2*)g_sfeat)[i];
    float2 fv = __half22float2(hv);
    fv.x *= d; fv.y *= d;
    ((__half2*)g_sfeat)[i] = __float22half2_rn(fv);
}

// fill body: atomic-free CSR fill using precomputed ranks
__device__ __forceinline__ void fill_body(const int* __restrict__ ei, int E,
                                          int N, int blk) {
    int t = blk * 256 + threadIdx.x;
    int E4 = E >> 2;
    if (t < E4) {
        int4 s = ((const int4*)ei)[t];
        int4 d = ((const int4*)(ei + E))[t];
        int4 r = ((const int4*)g_rank)[t];
        if ((unsigned)d.x < (unsigned)N) g_srcidx[g_off[d.x] + r.x] = s.x;
        if ((unsigned)d.y < (unsigned)N) g_srcidx[g_off[d.y] + r.y] = s.y;
        if ((unsigned)d.z < (unsigned)N) g_srcidx[g_off[d.z] + r.z] = s.z;
        if ((unsigned)d.w < (unsigned)N) g_srcidx[g_off[d.w] + r.w] = s.w;
    }
    if (t == 0)
        for (int e = E4 * 4; e < E; e++) {
            int s = ei[e], d = ei[E + e];
            if ((unsigned)d < (unsigned)N) g_srcidx[g_off[d] + g_rank[e]] = s;
        }
}

// K4: scale || fill (both depend only on scan)
__global__ void k_scalefill(const int* __restrict__ ei, int E, int N,
                            int nScaleBlk) {
    if ((int)blockIdx.x < nScaleBlk) scale_body(N, blockIdx.x);
    else                             fill_body(ei, E, N, blockIdx.x - nScaleBlk);
}

// K5: fused gather + gram + (last block) MLP.
__global__ void k_gathergram(int N,
                             const float* __restrict__ W1,
                             const float* __restrict__ b1,
                             const float* __restrict__ W2,
                             const float* __restrict__ b2,
                             float* __restrict__ out) {
    __shared__ float sy[32 * 29];
    __shared__ float sg[784];
    __shared__ float swacc[8];
    __shared__ int   s_last;
    int tid = threadIdx.x;
    int warp = tid >> 5, lane = tid & 31;
    int base = blockIdx.x * 32;

#pragma unroll
    for (int k = 0; k < 4; k++) {
        int local = warp * 4 + k;
        int node = base + local;
        float r = 0.f;
        if (node < N) {
            int off = g_off[node];
            int nxt = (node + 1 < N) ? g_off[node + 1] : off;
            int cnt;
            // cnt from offsets when possible; g_cnt was consumed as rank base,
            // so recompute from dinv: deg+1 = 1/dinv^2
            float di = g_dinv[node];
            cnt = (node + 1 < N) ? (nxt - off)
                                 : (int)(1.0f / (di * di) + 0.5f) - 1;
            float acc = __half2float(g_sfeat[(size_t)node * STRIDE + lane]);
            int i = 0;
            for (; i + 4 <= cnt; i += 4) {
                int s0 = g_srcidx[off + i];
                int s1 = g_srcidx[off + i + 1];
                int s2 = g_srcidx[off + i + 2];
                int s3 = g_srcidx[off + i + 3];
                float f0 = __half2float(g_sfeat[(size_t)s0 * STRIDE + lane]);
                float f1 = __half2float(g_sfeat[(size_t)s1 * STRIDE + lane]);
                float f2 = __half2float(g_sfeat[(size_t)s2 * STRIDE + lane]);
                float f3 = __half2float(g_sfeat[(size_t)s3 * STRIDE + lane]);
                acc += (f0 + f1) + (f2 + f3);
            }
            for (; i < cnt; i++)
                acc += __half2float(g_sfeat[(size_t)g_srcidx[off + i] * STRIDE + lane]);
            r = fmaxf(di * acc, 0.f);
        }
        if (lane < NPAIR) sy[local * 29 + lane] = r;
    }
    __syncthreads();

#pragma unroll
    for (int k = 0; k < 4; k++) {
        int e = tid + k * 256;
        if (e < 784) {
            int i = e / 28, j = e - i * 28;
            float a = 0.f;
#pragma unroll
            for (int nn = 0; nn < 32; nn++)
                a += sy[nn * 29 + i] * sy[nn * 29 + j];
            atomicAdd(&g_G[e], a);
        }
    }

    __threadfence();
    if (tid == 0) {
        int old = atomicAdd(&g_tick, 1);
        s_last = (old == gridDim.x - 1);
    }
    __syncthreads();
    if (!s_last) return;

    for (int i = tid; i < 784; i += 256) sg[i] = __ldcg(&g_G[i]);
    __syncthreads();
    float wacc = 0.f;
#pragma unroll
    for (int o = 0; o < 16; o++) {
        int r = warp * 16 + o;
        const float* wr = W1 + (size_t)r * 784;
        float dot = 0.f;
        for (int m = lane; m < 784; m += 32) dot += wr[m] * sg[m];
#pragma unroll
        for (int off = 16; off; off >>= 1)
            dot += __shfl_xor_sync(~0u, dot, off);
        if (lane == 0) wacc += fmaxf(dot + b1[r], 0.f) * W2[r];
    }
    if (lane == 0) swacc[warp] = wacc;
    __syncthreads();
    if (tid == 0) {
        float z = b2[0];
#pragma unroll
        for (int w = 0; w < 8; w++) z += swacc[w];
        out[0] = 1.f / (1.f + expf(-z));
    }
}

extern "C" void kernel_launch(void* const* d_in, const int* in_sizes, int n_in,
                              void* d_out, int out_size) {
    const float* x  = (const float*)d_in[0];
    const int*   ei = (const int*)d_in[1];     // int32 (JAX x64 disabled)
    const float* qw = (const float*)d_in[2];
    const float* W1 = (const float*)d_in[3];
    const float* b1 = (const float*)d_in[4];
    const float* W2 = (const float*)d_in[5];
    const float* b2 = (const float*)d_in[6];
    int N = in_sizes[0] / NF;
    int E = in_sizes[1] / 2;
    int E4 = E >> 2;
    int E8 = E >> 3;
    int ntiles = (N + TILE - 1) / TILE;
    int nFeatBlk  = (N + 31) / 32;
    int nHistBlk  = (E8 + 255) / 256;
    int nScaleBlk = (N * (STRIDE / 2) + 255) / 256;
    int nFillBlk  = (E4 + 255) / 256;

    k_setup     <<<(N + 255) / 256, 256>>>(qw, N);
    k_feathist  <<<nFeatBlk + nHistBlk, 256>>>(x, ei + E, E, N, nFeatBlk);
    k_scan      <<<ntiles, 1024>>>(N);
    k_scalefill <<<nScaleBlk + nFillBlk, 256>>>(ei, E, N, nScaleBlk);
    k_gathergram<<<(N + 31) / 32, 256>>>(N, W1, b1, W2, b2, (float*)d_out);
}